// round 7
// baseline (speedup 1.0000x reference)
#include <cuda_runtime.h>
#include <cstdint>

// Problem constants
#define K_NODES 100000
#define K_RELS  500
#define K_MEM   512
#define K_IN    1024
#define K_BATCH 65536

// GEMM tiling
#define BM 128
#define BN 256
#define BK 32
#define STR 36                       // floats/row (144 B) — ldmatrix conflict-free
#define A_TILE (BM * STR)            // 4608 floats
#define B_TILE (BN * STR)            // 9216 floats
#define STAGE_FLOATS (A_TILE + B_TILE)
#define STAGE_BYTES (STAGE_FLOATS * 4)      // 55296
#define NSTAGE 3
#define SMEM_BYTES (NSTAGE * STAGE_BYTES)   // 165888
#define NIT (K_IN / BK)              // 32 k-chunks

__device__ __forceinline__ int decode_time(const void* p) {
    int i = *(const int*)p;
    if (i < 0 || i > 1000000) i = (int)__int_as_float(i);
    return i;
}

// ---------------------------------------------------------------------------
// Kernel 1: out[concat(entity, rel)] = memory * (t/(t+1) if t>1 else 1)
// ---------------------------------------------------------------------------
__global__ void init_out_kernel(const float* __restrict__ ent,
                                const float* __restrict__ rel,
                                const void* __restrict__ tp,
                                float* __restrict__ out) {
    const int t = decode_time(tp);
    const float s = (t > 1) ? (float)t / (float)(t + 1) : 1.0f;
    const long nent = (long)K_NODES * K_MEM;
    const long ntot = nent + (long)K_RELS * K_MEM;
    long i = ((long)blockIdx.x * blockDim.x + threadIdx.x) * 4;
    const long stride = (long)gridDim.x * blockDim.x * 4;
    for (; i < ntot; i += stride) {
        const float4 v = (i < nent) ? *(const float4*)(ent + i)
                                    : *(const float4*)(rel + (i - nent));
        float4 o;
        o.x = v.x * s; o.y = v.y * s; o.z = v.z * s; o.w = v.w * s;
        *(float4*)(out + i) = o;
    }
}

// ---------------------------------------------------------------------------
// Kernel 2: C = X @ W^T (+bias), scaled by 1/(t+1), scatter-added into out.
// tf32 mma.sync + cvt.rna; ldmatrix fragments; warp tile m64n64 (128 accs,
// 255-reg budget, 1 CTA/SM); 3-stage cp.async ring; fragment prefetch.
// grid = (MEM/BN=2, BATCH/BM=512, 2), col tiles fastest.
// ---------------------------------------------------------------------------
__device__ __forceinline__ uint32_t f2tf(float f) {
    uint32_t u;
    asm("cvt.rna.tf32.f32 %0, %1;" : "=r"(u) : "f"(f));
    return u;
}
__device__ __forceinline__ void cp16(void* smem_dst, const void* gsrc) {
    uint32_t d = (uint32_t)__cvta_generic_to_shared(smem_dst);
    asm volatile("cp.async.cg.shared.global [%0], [%1], 16;" :: "r"(d), "l"(gsrc));
}
__device__ __forceinline__ void ldsm4(uint32_t& r0, uint32_t& r1,
                                      uint32_t& r2, uint32_t& r3, uint32_t a) {
    asm volatile("ldmatrix.sync.aligned.m8n8.x4.shared.b16 {%0,%1,%2,%3}, [%4];"
                 : "=r"(r0), "=r"(r1), "=r"(r2), "=r"(r3) : "r"(a));
}

__global__ __launch_bounds__(256, 1) void gemm_scatter_kernel(
    const float* __restrict__ Xn, const float* __restrict__ Xr,
    const float* __restrict__ Wn, const float* __restrict__ Wr,
    const float* __restrict__ bn, const float* __restrict__ br,
    const int* __restrict__ idn, const int* __restrict__ idr,
    const void* __restrict__ tp, float* __restrict__ out)
{
    extern __shared__ float smem[];   // 3 stages of [A | B]

    const int z = blockIdx.z;
    const float* __restrict__ X    = z ? Xr  : Xn;
    const float* __restrict__ W    = z ? Wr  : Wn;
    const float* __restrict__ bias = z ? br  : bn;
    const int*   __restrict__ ids  = z ? idr : idn;
    const int obase = z ? K_NODES : 0;

    const int t = decode_time(tp);
    const float inv = 1.0f / (float)(t + 1);

    const int bm    = blockIdx.y * BM;
    const int bnoff = blockIdx.x * BN;
    const int tid  = threadIdx.x;
    const int wid  = tid >> 5, lane = tid & 31;
    const int wm = (wid & 1) * 64;        // 2 warp rows
    const int wn = (wid >> 1) * 64;       // 4 warp cols
    const int grp = lane >> 2, tig = lane & 3;

    // ldmatrix per-lane offsets (bytes), same mapping as validated in R6
    const uint32_t aoff =
        ((((lane & 7) + ((lane >> 3) & 1) * 8) * STR) + ((lane >> 4) & 1) * 4) * 4;
    const uint32_t boff =
        ((((lane & 7) + ((lane >> 4) & 1) * 8) * STR) + ((lane >> 3) & 1) * 4) * 4;

    const uint32_t smem0 = (uint32_t)__cvta_generic_to_shared(smem);
    const uint32_t aBase0 = smem0 + (uint32_t)(wm * STR * 4) + aoff;
    const uint32_t bBase0 = smem0 + (uint32_t)(A_TILE * 4) + (uint32_t)(wn * STR * 4) + boff;

    // Incremental fill pointers
    const char* gA = (const char*)(X + (size_t)(bm    + (tid >> 3)) * K_IN + ((tid & 7) << 2));
    const char* gB = (const char*)(W + (size_t)(bnoff + (tid >> 3)) * K_IN + ((tid & 7) << 2));
    const int sdst = (tid >> 3) * STR + ((tid & 7) << 2);

    auto fill = [&](int st) {
        float* dA = smem + st * STAGE_FLOATS + sdst;
        float* dB = dA + A_TILE;
        #pragma unroll
        for (int i = 0; i < 4; i++)                       // A: 128 rows
            cp16(dA + i * 32 * STR, gA + (size_t)i * 32 * K_IN * 4);
        #pragma unroll
        for (int i = 0; i < 8; i++)                       // B: 256 rows
            cp16(dB + i * 32 * STR, gB + (size_t)i * 32 * K_IN * 4);
        asm volatile("cp.async.commit_group;");
        gA += BK * 4;
        gB += BK * 4;
    };

    float acc[4][8][4] = {};   // 128 accumulators (m64 x n64)

    fill(0); fill(1);

    uint32_t af[2][4][4], bf[2][4][4];

    auto load_frags = [&](uint32_t aB, uint32_t bB, int ks, int pb) {
        #pragma unroll
        for (int mt = 0; mt < 4; ++mt) {
            uint32_t r0, r1, r2, r3;
            ldsm4(r0, r1, r2, r3, aB + mt * (16 * STR * 4) + ks * 32);
            af[pb][mt][0] = f2tf(__uint_as_float(r0));
            af[pb][mt][1] = f2tf(__uint_as_float(r1));
            af[pb][mt][2] = f2tf(__uint_as_float(r2));
            af[pb][mt][3] = f2tf(__uint_as_float(r3));
        }
        #pragma unroll
        for (int np = 0; np < 4; ++np) {
            uint32_t r0, r1, r2, r3;
            ldsm4(r0, r1, r2, r3, bB + np * (16 * STR * 4) + ks * 32);
            bf[pb][np][0] = f2tf(__uint_as_float(r0));   // n-tile 2np   lo
            bf[pb][np][1] = f2tf(__uint_as_float(r1));   // n-tile 2np   hi
            bf[pb][np][2] = f2tf(__uint_as_float(r2));   // n-tile 2np+1 lo
            bf[pb][np][3] = f2tf(__uint_as_float(r3));   // n-tile 2np+1 hi
        }
    };

    for (int it = 0; it < NIT; ++it) {
        const int st = it % 3;
        asm volatile("cp.async.wait_group 1;");
        __syncthreads();

        // Refill the stage 2 ahead (distinct from current & next in mod-3 ring)
        if (it + 2 < NIT) fill((it + 2) % 3);
        else asm volatile("cp.async.commit_group;");

        const uint32_t aB = aBase0 + st * STAGE_BYTES;
        const uint32_t bB = bBase0 + st * STAGE_BYTES;

        load_frags(aB, bB, 0, 0);
        #pragma unroll
        for (int ks = 0; ks < 4; ++ks) {
            if (ks < 3) load_frags(aB, bB, ks + 1, (ks + 1) & 1);
            const int pb = ks & 1;
            #pragma unroll
            for (int mt = 0; mt < 4; ++mt)
                #pragma unroll
                for (int nt = 0; nt < 8; ++nt)
                    asm volatile(
                        "mma.sync.aligned.m16n8k8.row.col.f32.tf32.tf32.f32 "
                        "{%0,%1,%2,%3}, {%4,%5,%6,%7}, {%8,%9}, {%0,%1,%2,%3};"
                        : "+f"(acc[mt][nt][0]), "+f"(acc[mt][nt][1]),
                          "+f"(acc[mt][nt][2]), "+f"(acc[mt][nt][3])
                        : "r"(af[pb][mt][0]), "r"(af[pb][mt][1]),
                          "r"(af[pb][mt][2]), "r"(af[pb][mt][3]),
                          "r"(bf[pb][nt >> 1][(nt & 1) * 2]),
                          "r"(bf[pb][nt >> 1][(nt & 1) * 2 + 1]));
        }
    }

    // Epilogue: (acc + bias) * inv, scatter-add via float2 vector atomics
    float2 bv[8];
    #pragma unroll
    for (int nt = 0; nt < 8; ++nt) {
        int col = bnoff + wn + nt * 8 + tig * 2;
        bv[nt].x = bias[col];
        bv[nt].y = bias[col + 1];
    }
    #pragma unroll
    for (int mt = 0; mt < 4; ++mt) {
        #pragma unroll
        for (int h = 0; h < 2; ++h) {
            const int gb = bm + wm + mt * 16 + grp + h * 8;
            const long orow = (long)(ids[gb] + obase);
            float* dst = out + orow * K_MEM;
            #pragma unroll
            for (int nt = 0; nt < 8; ++nt) {
                const int col = bnoff + wn + nt * 8 + tig * 2;
                float2 v;
                v.x = (acc[mt][nt][h * 2 + 0] + bv[nt].x) * inv;
                v.y = (acc[mt][nt][h * 2 + 1] + bv[nt].y) * inv;
                atomicAdd((float2*)(dst + col), v);
            }
        }
    }
}

// ---------------------------------------------------------------------------
extern "C" void kernel_launch(void* const* d_in, const int* in_sizes, int n_in,
                              void* d_out, int out_size) {
    const float* Xn  = (const float*)d_in[0];
    const float* Xr  = (const float*)d_in[1];
    const int*   idn = (const int*)  d_in[2];
    const int*   idr = (const int*)  d_in[3];
    const float* ent = (const float*)d_in[4];
    const float* rel = (const float*)d_in[5];
    const float* Wn  = (const float*)d_in[6];
    const float* bn  = (const float*)d_in[7];
    const float* Wr  = (const float*)d_in[8];
    const float* br  = (const float*)d_in[9];
    const void*  tp  = d_in[10];
    float* out = (float*)d_out;

    init_out_kernel<<<1184, 256>>>(ent, rel, tp, out);

    cudaFuncSetAttribute(gemm_scatter_kernel,
                         cudaFuncAttributeMaxDynamicSharedMemorySize, SMEM_BYTES);
    dim3 grid(K_MEM / BN, K_BATCH / BM, 2);
    gemm_scatter_kernel<<<grid, 256, SMEM_BYTES>>>(
        Xn, Xr, Wn, Wr, bn, br, idn, idr, tp, out);
}

// round 9
// speedup vs baseline: 1.1139x; 1.1139x over previous
#include <cuda_runtime.h>
#include <cstdint>

// Problem constants
#define K_NODES 100000
#define K_RELS  500
#define K_MEM   512
#define K_IN    1024
#define K_BATCH 65536

// GEMM tiling (R6 structure + 3-stage ring)
#define BM 128
#define BN 128
#define BK 32
#define STR 36                       // floats/row (144 B) — ldmatrix conflict-free
#define A_TILE (BM * STR)            // 4608 floats
#define B_TILE (BN * STR)            // 4608 floats
#define STAGE_FLOATS (A_TILE + B_TILE)
#define STAGE_BYTES (STAGE_FLOATS * 4)       // 36864
#define NSTAGE 3
#define SMEM_BYTES (NSTAGE * STAGE_BYTES)    // 110592
#define NIT (K_IN / BK)              // 32 k-chunks

// Pre-converted (tf32) weights scratch: [2][512][1024] = 4 MB
__device__ uint32_t g_Wc[2 * K_MEM * K_IN];

__device__ __forceinline__ int decode_time(const void* p) {
    int i = *(const int*)p;
    if (i < 0 || i > 1000000) i = (int)__int_as_float(i);
    return i;
}
__device__ __forceinline__ uint32_t f2tf(float f) {
    uint32_t u;
    asm("cvt.rna.tf32.f32 %0, %1;" : "=r"(u) : "f"(f));
    return u;
}

// ---------------------------------------------------------------------------
// Kernel 0: convert W_node / W_rel to tf32 bits in g_Wc
// ---------------------------------------------------------------------------
__global__ void conv_w_kernel(const float* __restrict__ Wn,
                              const float* __restrict__ Wr) {
    const int i = blockIdx.x * blockDim.x + threadIdx.x;     // float4 index
    const float4 v = ((const float4*)(blockIdx.y ? Wr : Wn))[i];
    uint4 o;
    o.x = f2tf(v.x); o.y = f2tf(v.y); o.z = f2tf(v.z); o.w = f2tf(v.w);
    ((uint4*)(g_Wc + (size_t)blockIdx.y * K_MEM * K_IN))[i] = o;
}

// ---------------------------------------------------------------------------
// Kernel 1: out[concat(entity, rel)] = memory * (t/(t+1) if t>1 else 1)
// ---------------------------------------------------------------------------
__global__ void init_out_kernel(const float* __restrict__ ent,
                                const float* __restrict__ rel,
                                const void* __restrict__ tp,
                                float* __restrict__ out) {
    const int t = decode_time(tp);
    const float s = (t > 1) ? (float)t / (float)(t + 1) : 1.0f;
    const long nent = (long)K_NODES * K_MEM;
    const long ntot = nent + (long)K_RELS * K_MEM;
    long i = ((long)blockIdx.x * blockDim.x + threadIdx.x) * 4;
    const long stride = (long)gridDim.x * blockDim.x * 4;
    for (; i < ntot; i += stride) {
        const float4 v = (i < nent) ? *(const float4*)(ent + i)
                                    : *(const float4*)(rel + (i - nent));
        float4 o;
        o.x = v.x * s; o.y = v.y * s; o.z = v.z * s; o.w = v.w * s;
        *(float4*)(out + i) = o;
    }
}

// ---------------------------------------------------------------------------
// Kernel 2: C = X @ W^T (+bias), scaled by 1/(t+1), scatter-added into out.
// tf32 mma.sync; A fragments ldmatrix+cvt.rna, B fragments ldmatrix from
// pre-converted tf32 weights (no CVT). 3-stage cp.async ring, ONE barrier
// per k-chunk. grid = (MEM/BN, BATCH/BM, 2), col tiles fastest (L2 reuse).
// ---------------------------------------------------------------------------
__device__ __forceinline__ void cp16(void* smem_dst, const void* gsrc) {
    uint32_t d = (uint32_t)__cvta_generic_to_shared(smem_dst);
    asm volatile("cp.async.cg.shared.global [%0], [%1], 16;" :: "r"(d), "l"(gsrc));
}
__device__ __forceinline__ void ldsm4(uint32_t& r0, uint32_t& r1,
                                      uint32_t& r2, uint32_t& r3, uint32_t a) {
    asm volatile("ldmatrix.sync.aligned.m8n8.x4.shared.b16 {%0,%1,%2,%3}, [%4];"
                 : "=r"(r0), "=r"(r1), "=r"(r2), "=r"(r3) : "r"(a));
}

__global__ __launch_bounds__(256, 2) void gemm_scatter_kernel(
    const float* __restrict__ Xn, const float* __restrict__ Xr,
    const float* __restrict__ bn, const float* __restrict__ br,
    const int* __restrict__ idn, const int* __restrict__ idr,
    const void* __restrict__ tp, float* __restrict__ out)
{
    extern __shared__ float smem[];   // 3 stages of [A | B]

    const int z = blockIdx.z;
    const float*    __restrict__ X    = z ? Xr : Xn;
    const uint32_t* __restrict__ W    = g_Wc + (size_t)z * K_MEM * K_IN;
    const float*    __restrict__ bias = z ? br : bn;
    const int*      __restrict__ ids  = z ? idr : idn;
    const int obase = z ? K_NODES : 0;

    const int t = decode_time(tp);
    const float inv = 1.0f / (float)(t + 1);

    const int bm    = blockIdx.y * BM;
    const int bnoff = blockIdx.x * BN;
    const int tid  = threadIdx.x;
    const int wid  = tid >> 5, lane = tid & 31;
    const int wm = (wid & 1) * 64;
    const int wn = (wid >> 1) * 32;
    const int grp = lane >> 2, tig = lane & 3;

    // ldmatrix per-lane offsets (bytes) — mapping validated in R6
    const uint32_t aoff =
        ((((lane & 7) + ((lane >> 3) & 1) * 8) * STR) + ((lane >> 4) & 1) * 4) * 4;
    const uint32_t boff =
        ((((lane & 7) + ((lane >> 4) & 1) * 8) * STR) + ((lane >> 3) & 1) * 4) * 4;

    const uint32_t smem0 = (uint32_t)__cvta_generic_to_shared(smem);
    const uint32_t aBase0 = smem0 + (uint32_t)(wm * STR * 4) + aoff;
    const uint32_t bBase0 = smem0 + (uint32_t)(A_TILE * 4) + (uint32_t)(wn * STR * 4) + boff;

    // Incremental fill pointers: thread covers row tid>>3 (+i*32), 16B chunk tid&7
    const char* gA = (const char*)(X + (size_t)(bm    + (tid >> 3)) * K_IN + ((tid & 7) << 2));
    const char* gB = (const char*)(W + (size_t)(bnoff + (tid >> 3)) * K_IN + ((tid & 7) << 2));
    const int sdst = (tid >> 3) * STR + ((tid & 7) << 2);

    auto fill = [&](int st) {
        float* dA = smem + st * STAGE_FLOATS + sdst;
        float* dB = dA + A_TILE;
        #pragma unroll
        for (int i = 0; i < 4; i++)
            cp16(dA + i * 32 * STR, gA + (size_t)i * 32 * K_IN * 4);
        #pragma unroll
        for (int i = 0; i < 4; i++)
            cp16(dB + i * 32 * STR, gB + (size_t)i * 32 * K_IN * 4);
        asm volatile("cp.async.commit_group;");
        gA += BK * 4;
        gB += BK * 4;
    };

    float acc[4][4][4] = {};   // 64 accumulators (m64 x n32)

    fill(0); fill(1);

    for (int it = 0; it < NIT; ++it) {
        const int st = it % 3;
        asm volatile("cp.async.wait_group 1;");
        __syncthreads();                       // single barrier per iter

        // Refill stage 2 ahead (ring: never the stage being read now or next)
        if (it + 2 < NIT) fill((it + 2) % 3);
        else asm volatile("cp.async.commit_group;");

        const uint32_t aB = aBase0 + st * STAGE_BYTES;
        const uint32_t bB = bBase0 + st * STAGE_BYTES;

        #pragma unroll
        for (int ks = 0; ks < 4; ++ks) {
            uint32_t af[4][4], bf[4][2];
            #pragma unroll
            for (int mt = 0; mt < 4; ++mt) {
                uint32_t r0, r1, r2, r3;
                ldsm4(r0, r1, r2, r3, aB + mt * (16 * STR * 4) + ks * 32);
                af[mt][0] = f2tf(__uint_as_float(r0));
                af[mt][1] = f2tf(__uint_as_float(r1));
                af[mt][2] = f2tf(__uint_as_float(r2));
                af[mt][3] = f2tf(__uint_as_float(r3));
            }
            #pragma unroll
            for (int np = 0; np < 2; ++np) {
                uint32_t r0, r1, r2, r3;
                ldsm4(r0, r1, r2, r3, bB + np * (16 * STR * 4) + ks * 32);
                bf[2 * np][0]     = r0;        // already tf32 bits
                bf[2 * np][1]     = r1;
                bf[2 * np + 1][0] = r2;
                bf[2 * np + 1][1] = r3;
            }
            #pragma unroll
            for (int mt = 0; mt < 4; ++mt)
                #pragma unroll
                for (int nt = 0; nt < 4; ++nt)
                    asm volatile(
                        "mma.sync.aligned.m16n8k8.row.col.f32.tf32.tf32.f32 "
                        "{%0,%1,%2,%3}, {%4,%5,%6,%7}, {%8,%9}, {%0,%1,%2,%3};"
                        : "+f"(acc[mt][nt][0]), "+f"(acc[mt][nt][1]),
                          "+f"(acc[mt][nt][2]), "+f"(acc[mt][nt][3])
                        : "r"(af[mt][0]), "r"(af[mt][1]), "r"(af[mt][2]), "r"(af[mt][3]),
                          "r"(bf[nt][0]), "r"(bf[nt][1]));
        }
    }

    // Epilogue: (acc + bias) * inv, scatter-add via float2 vector atomics
    float2 bv[4];
    #pragma unroll
    for (int nt = 0; nt < 4; ++nt) {
        int col = bnoff + wn + nt * 8 + tig * 2;
        bv[nt].x = bias[col];
        bv[nt].y = bias[col + 1];
    }
    #pragma unroll
    for (int mt = 0; mt < 4; ++mt) {
        #pragma unroll
        for (int h = 0; h < 2; ++h) {
            const int gb = bm + wm + mt * 16 + grp + h * 8;
            const long orow = (long)(ids[gb] + obase);
            float* dst = out + orow * K_MEM;
            #pragma unroll
            for (int nt = 0; nt < 4; ++nt) {
                const int col = bnoff + wn + nt * 8 + tig * 2;
                float2 v;
                v.x = (acc[mt][nt][h * 2 + 0] + bv[nt].x) * inv;
                v.y = (acc[mt][nt][h * 2 + 1] + bv[nt].y) * inv;
                atomicAdd((float2*)(dst + col), v);
            }
        }
    }
}

// ---------------------------------------------------------------------------
extern "C" void kernel_launch(void* const* d_in, const int* in_sizes, int n_in,
                              void* d_out, int out_size) {
    const float* Xn  = (const float*)d_in[0];
    const float* Xr  = (const float*)d_in[1];
    const int*   idn = (const int*)  d_in[2];
    const int*   idr = (const int*)  d_in[3];
    const float* ent = (const float*)d_in[4];
    const float* rel = (const float*)d_in[5];
    const float* Wn  = (const float*)d_in[6];
    const float* bn  = (const float*)d_in[7];
    const float* Wr  = (const float*)d_in[8];
    const float* br  = (const float*)d_in[9];
    const void*  tp  = d_in[10];
    float* out = (float*)d_out;

    // 0) W -> tf32 scratch  (512*1024/4 float4 per matrix / 256 thr = 512 blocks)
    conv_w_kernel<<<dim3(K_MEM * K_IN / 4 / 256, 2), 256>>>(Wn, Wr);

    // 1) out = scaled memory state
    init_out_kernel<<<1184, 256>>>(ent, rel, tp, out);

    // 2) GEMM + scatter-add
    cudaFuncSetAttribute(gemm_scatter_kernel,
                         cudaFuncAttributeMaxDynamicSharedMemorySize, SMEM_BYTES);
    dim3 grid(K_MEM / BN, K_BATCH / BM, 2);
    gemm_scatter_kernel<<<grid, 256, SMEM_BYTES>>>(
        Xn, Xr, bn, br, idn, idr, tp, out);
}